// round 17
// baseline (speedup 1.0000x reference)
#include <cuda_runtime.h>
#include <math.h>

#define Bq 4
#define Nq 512
#define DIN 128
#define F 64
#define NN (Nq*Nq)
#define ALPHA 0.2f
#define MSPLIT 2
#define MCHUNK (Nq/MSPLIT)     // 256
#define NR (Bq*Nq)             // 2048 rows

// scratch (plain stores only)
__device__ float g_h [NR*F];
__device__ float g_s1[NR];
__device__ float g_t [NR];
__device__ float g_part[MSPLIT*NR*F];      // AV partials
__device__ float g_psum[MSPLIT*NR];        // row-sum partials

// ---------------------------------------------------------------------------
// Kernel A: h = x@W + b ; s1 ; t.  W in smem; 8 rows/block; 512 thr;
// warp = (row, k-half): 2 warps per row, 64 k each; smem combine.
// Grid 256 = 4096 warps.
// ---------------------------------------------------------------------------
__global__ __launch_bounds__(512) void gat_h_kernel(
    const float* __restrict__ x, const float* __restrict__ W,
    const float* __restrict__ bias, const float* __restrict__ a)
{
    __shared__ __align__(16) float xs[8*DIN];     // 4KB
    __shared__ __align__(16) float Ws[DIN*F];     // 32KB
    __shared__ __align__(16) float2 ps[8][32];    // 2KB k-half partials

    int tid  = threadIdx.x;
    int row0 = blockIdx.x * 8;

    if (tid < 256)
        ((float4*)xs)[tid] = ((const float4*)(x + (long)row0*DIN))[tid];
    {
        const float4* wsrc = (const float4*)W;
        float4* wdst = (float4*)Ws;
        #pragma unroll
        for (int i = 0; i < 4; ++i)
            wdst[tid + 512*i] = wsrc[tid + 512*i];
    }
    __syncthreads();

    int lane = tid & 31;               // float2 feature pair 0..31
    int wid  = tid >> 5;               // 0..15
    int r    = wid >> 1;               // row 0..7
    int kh   = wid & 1;                // k-half

    float2 acc = make_float2(0.f, 0.f);
    const float2* Ws2 = (const float2*)Ws;
    const float*  xr  = xs + r*DIN + kh*64;

    #pragma unroll 8
    for (int kl = 0; kl < 64; ++kl) {
        int k = kh*64 + kl;
        float2 w  = Ws2[k*32 + lane];
        float  xk = xr[kl];
        acc.x += xk*w.x; acc.y += xk*w.y;
    }

    if (kh) ps[r][lane] = acc;
    __syncthreads();

    if (!kh) {
        float2 p  = ps[r][lane];
        float2 bv = ((const float2*)bias)[lane];
        acc.x += p.x + bv.x;
        acc.y += p.y + bv.y;

        ((float2*)g_h)[(long)(row0 + r)*32 + lane] = acc;

        float2 a1 = ((const float2*)a)[lane];
        float2 a2 = ((const float2*)a)[32 + lane];
        float s1 = acc.x*a1.x + acc.y*a1.y;
        float t  = acc.x*a2.x + acc.y*a2.y;
        #pragma unroll
        for (int o = 16; o; o >>= 1) {
            s1 += __shfl_xor_sync(0xffffffffu, s1, o);
            t  += __shfl_xor_sync(0xffffffffu, t,  o);
        }
        if (lane == 0) { g_s1[row0 + r] = s1; g_t[row0 + r] = t; }
    }
}

// ---------------------------------------------------------------------------
// Kernel B: 8 rows x 256-m chunk per block. 256 threads, grid 512.
// Fused: masked exp(leakyrelu(logits)) + row sums + partial AV.
// ---------------------------------------------------------------------------
__global__ __launch_bounds__(256) void gat_attn_kernel(const int* __restrict__ adj)
{
    __shared__ float s1s[Nq];
    __shared__ float ts [Nq];
    __shared__ __align__(16) float buf[4096];   // probs[8][256] (8KB) then red (16KB)
    float (*probs)[MCHUNK] = (float(*)[MCHUNK])buf;

    int tid  = threadIdx.x;
    int lane = tid & 31;
    int wid  = tid >> 5;                 // 0..7
    int bid  = blockIdx.x;
    int ms   = bid & 1;
    int rb   = (bid >> 1) & 63;
    int b    = bid >> 7;
    int n0   = rb << 3;
    int m0   = ms * MCHUNK;

    for (int i = tid; i < Nq; i += 256) {
        s1s[i] = g_s1[b*Nq + i];
        ts [i] = g_t [b*Nq + i];
    }
    __syncthreads();

    // ---- phase 1: exp(leakyrelu(logits)) masked, + row partial sums ----
    {
        int n  = n0 + wid;
        int ma = m0 + lane*8;            // 8 m per thread
        const int4* ap = (const int4*)(adj + ((long)b*Nq + n)*Nq + ma);
        int4 av0 = ap[0], av1 = ap[1];
        int avv[8] = {av0.x,av0.y,av0.z,av0.w,av1.x,av1.y,av1.z,av1.w};
        float sum = 0.f;
        float pv[8];
        #pragma unroll
        for (int j = 0; j < 8; ++j) {
            int m  = ma + j;
            int q1 = 2*(n*Nq + m);
            int idx1 = (q1   < NN) ? (q1   >> 9) : ((q1   - NN) & (Nq-1));
            int idx2 = (q1+1 < NN) ? ((q1+1)>> 9) : ((q1+1 - NN) & (Nq-1));
            float e = s1s[idx1] + ts[idx2];
            e = (e > 0.0f) ? e : ALPHA*e;
            float p = (avv[j] > 0) ? __expf(e) : 0.0f;
            pv[j] = p; sum += p;
        }
        int mloc = lane*8;
        *(float4*)&probs[wid][mloc]     = make_float4(pv[0],pv[1],pv[2],pv[3]);
        *(float4*)&probs[wid][mloc + 4] = make_float4(pv[4],pv[5],pv[6],pv[7]);
        #pragma unroll
        for (int o = 16; o; o >>= 1) sum += __shfl_xor_sync(0xffffffffu, sum, o);
        if (lane == 0) g_psum[(ms*Bq + b)*Nq + n] = sum;
    }
    __syncthreads();

    // ---- phase 2: partial AV. warp = 32 contiguous m, lane = f2 ----
    float2 acc[8];
    #pragma unroll
    for (int r = 0; r < 8; ++r) acc[r] = make_float2(0.f, 0.f);

    const float2* h2 = (const float2*)(g_h + (long)b*Nq*F);
    #pragma unroll
    for (int kcc = 0; kcc < 8; ++kcc) {
        int mloc = wid*32 + kcc*4;
        int mabs = m0 + mloc;
        float2 hv0 = h2[(mabs+0)*32 + lane];
        float2 hv1 = h2[(mabs+1)*32 + lane];
        float2 hv2 = h2[(mabs+2)*32 + lane];
        float2 hv3 = h2[(mabs+3)*32 + lane];
        #pragma unroll
        for (int r = 0; r < 8; ++r) {
            float4 p = *(const float4*)&probs[r][mloc];
            acc[r].x += p.x*hv0.x + p.y*hv1.x + p.z*hv2.x + p.w*hv3.x;
            acc[r].y += p.x*hv0.y + p.y*hv1.y + p.z*hv2.y + p.w*hv3.y;
        }
    }
    __syncthreads();                      // probs dead; buf becomes red (16KB)

    float2* red = (float2*)buf;           // [8 g][8 r][32 f2]
    #pragma unroll
    for (int r = 0; r < 8; ++r)
        red[(wid*8 + r)*32 + lane] = acc[r];
    __syncthreads();

    {
        int r = wid;
        float2 o = make_float2(0.f, 0.f);
        #pragma unroll
        for (int g = 0; g < 8; ++g) {
            float2 v = red[(g*8 + r)*32 + lane];
            o.x += v.x; o.y += v.y;
        }
        ((float2*)g_part)[((long)(ms*Bq + b)*Nq + n0 + r)*32 + lane] = o;
    }
}

// ---------------------------------------------------------------------------
// Kernel C: combine 2 partials + normalize + elu. Coalesced scalar.
// Grid 512 x 256 thr.
// ---------------------------------------------------------------------------
__global__ __launch_bounds__(256) void gat_combine_kernel(float* __restrict__ out)
{
    int gid = blockIdx.x*256 + threadIdx.x;   // 0..131071
    int row = gid >> 6;                       // F=64

    float acc = 0.f, s = 0.f;
    #pragma unroll
    for (int ms = 0; ms < MSPLIT; ++ms) {
        acc += g_part[(long)ms*NR*F + gid];
        s   += g_psum[ms*NR + row];
    }
    float v = acc / s;
    out[gid] = (v > 0.0f) ? v : expm1f(v);
}

// ---------------------------------------------------------------------------
extern "C" void kernel_launch(void* const* d_in, const int* in_sizes, int n_in,
                              void* d_out, int out_size)
{
    const float* x    = (const float*)d_in[0];
    const int*   adj  = (const int*)  d_in[1];
    const float* W    = (const float*)d_in[2];
    const float* bias = (const float*)d_in[3];
    const float* a    = (const float*)d_in[4];
    float* out = (float*)d_out;

    gat_h_kernel<<<NR/8, 512>>>(x, W, bias, a);
    gat_attn_kernel<<<Bq*64*MSPLIT, 256>>>(adj);
    gat_combine_kernel<<<(NR*F)/256, 256>>>(out);
}